// round 17
// baseline (speedup 1.0000x reference)
#include <cuda_runtime.h>
#include <math.h>

#define FULLMASK 0xffffffffu
typedef unsigned long long ull;

// RK45 tableau (Tsit5, as in the reference)
#define A21 0.161f
#define A31 ((float)(-0.008480655492356989))
#define A32 ((float)(0.335480655492357))
#define A41 ((float)(2.8971530571054935))
#define A42 ((float)(-6.359448489975075))
#define A43 ((float)(4.3622954328695815))
#define A51 ((float)(5.325864828439257))
#define A52 ((float)(-11.748883564062828))
#define A53 ((float)(7.4955393428898365))
#define A54 ((float)(-0.09249506636175525))
#define A61 ((float)(5.86145544294642))
#define A62 ((float)(-12.92096931784711))
#define A63 ((float)(8.159367898576159))
#define A64 ((float)(-0.071584973281401))
#define A65 ((float)(-0.028269050394068383))
#define B1  ((float)(0.09646076681806523))
#define B2  0.01f
#define B3  ((float)(0.4798896504144996))
#define B4  ((float)(1.379008574103742))
#define B5  ((float)(-3.290069515436081))
#define B6  ((float)(2.324710524099774))

static __device__ __forceinline__ float softplus_f(float x) {
    return fmaxf(x, 0.0f) + __logf(1.0f + __expf(-fabsf(x)));
}
static __device__ __forceinline__ float sigmoid_f(float x) {
    return 1.0f / (1.0f + __expf(-x));
}

static __device__ __forceinline__ ull pack2(float lo, float hi) {
    ull r;
    asm("mov.b64 %0, {%1, %2};" : "=l"(r) : "f"(lo), "f"(hi));
    return r;
}
static __device__ __forceinline__ void unpack2(ull v, float& lo, float& hi) {
    asm("mov.b64 {%0, %1}, %2;" : "=f"(lo), "=f"(hi) : "l"(v));
}
#define FMA2(acc, a, b) asm("fma.rn.f32x2 %0, %1, %2, %0;" : "+l"(acc) : "l"(a), "l"(b))
#define ADD2(d, a, b)   asm("add.rn.f32x2 %0, %1, %2;"     : "=l"(d)  : "l"(a), "l"(b))

// SEIR rhs (ee=0, q=0.5, dd=1, kk=0.526, aa=ii=0.244, p=0.667, f=0.98)
#define SRHS_B(bt_, S_, E_, I_, A_, dS_, dE_, dI_, dA_, dR_) do {     \
    float LL_  = fmaf(0.5f, (I_), (A_));                              \
    float bsl_ = ((bt_) * (S_)) * LL_;                                \
    dS_ = -bsl_;                                                      \
    dE_ = bsl_ - 0.526f * (E_);                                       \
    dI_ = (float)(0.667 * 0.526) * (E_) - 0.244f * (I_);              \
    dA_ = (float)((1.0 - 0.667) * 0.526) * (E_) - 0.244f * (A_);      \
    dR_ = (float)(0.98 * 0.244) * (I_) + 0.244f * (A_);               \
} while (0)

// One Tsit5 step of size h on (S,E,I,A,R) with constant beta
static __device__ __forceinline__ void seir_step(
    float h, float beta, float& S, float& E, float& I, float& A, float& R)
{
    float k1S,k1E,k1I,k1A,k1R, k2S,k2E,k2I,k2A,k2R, k3S,k3E,k3I,k3A,k3R;
    float k4S,k4E,k4I,k4A,k4R, k5S,k5E,k5I,k5A,k5R, k6S,k6E,k6I,k6A,k6R;
    float tS,tE,tI,tA;
    SRHS_B(beta, S,E,I,A, k1S,k1E,k1I,k1A,k1R);
    tS = fmaf(h*A21,k1S,S); tE = fmaf(h*A21,k1E,E);
    tI = fmaf(h*A21,k1I,I); tA = fmaf(h*A21,k1A,A);
    SRHS_B(beta, tS,tE,tI,tA, k2S,k2E,k2I,k2A,k2R);
    tS = fmaf(h, A31*k1S + A32*k2S, S); tE = fmaf(h, A31*k1E + A32*k2E, E);
    tI = fmaf(h, A31*k1I + A32*k2I, I); tA = fmaf(h, A31*k1A + A32*k2A, A);
    SRHS_B(beta, tS,tE,tI,tA, k3S,k3E,k3I,k3A,k3R);
    tS = fmaf(h, A41*k1S + A42*k2S + A43*k3S, S);
    tE = fmaf(h, A41*k1E + A42*k2E + A43*k3E, E);
    tI = fmaf(h, A41*k1I + A42*k2I + A43*k3I, I);
    tA = fmaf(h, A41*k1A + A42*k2A + A43*k3A, A);
    SRHS_B(beta, tS,tE,tI,tA, k4S,k4E,k4I,k4A,k4R);
    tS = fmaf(h, A51*k1S + A52*k2S + A53*k3S + A54*k4S, S);
    tE = fmaf(h, A51*k1E + A52*k2E + A53*k3E + A54*k4E, E);
    tI = fmaf(h, A51*k1I + A52*k2I + A53*k3I + A54*k4I, I);
    tA = fmaf(h, A51*k1A + A52*k2A + A53*k3A + A54*k4A, A);
    SRHS_B(beta, tS,tE,tI,tA, k5S,k5E,k5I,k5A,k5R);
    tS = fmaf(h, A61*k1S + A62*k2S + A63*k3S + A64*k4S + A65*k5S, S);
    tE = fmaf(h, A61*k1E + A62*k2E + A63*k3E + A64*k4E + A65*k5E, E);
    tI = fmaf(h, A61*k1I + A62*k2I + A63*k3I + A64*k4I + A65*k5I, I);
    tA = fmaf(h, A61*k1A + A62*k2A + A63*k3A + A64*k4A + A65*k5A, A);
    SRHS_B(beta, tS,tE,tI,tA, k6S,k6E,k6I,k6A,k6R);
    S = fmaf(h, B1*k1S + B2*k2S + B3*k3S + B4*k4S + B5*k5S + B6*k6S, S);
    E = fmaf(h, B1*k1E + B2*k2E + B3*k3E + B4*k4E + B5*k5E + B6*k6E, E);
    I = fmaf(h, B1*k1I + B2*k2I + B3*k3I + B4*k4I + B5*k5I + B6*k6I, I);
    A = fmaf(h, B1*k1A + B2*k2A + B3*k3A + B4*k4A + B5*k5A + B6*k6A, A);
    R = fmaf(h, B1*k1R + B2*k2R + B3*k3R + B4*k4R + B5*k5R + B6*k6R, R);
}

// 288 threads: warps 0-3 = W1+W0, warps 4-7 = W2+W3, warp 8 = bs+SEIR
__global__ __launch_bounds__(288, 1)
void ode_persistent_kernel(
    const float* __restrict__ y0,   const float* __restrict__ ts,
    const float* __restrict__ gW0,  const float* __restrict__ gb0,
    const float* __restrict__ gW1,  const float* __restrict__ gb1,
    const float* __restrict__ gW2,  const float* __restrict__ gb2,
    const float* __restrict__ gW3,  const float* __restrict__ gb3,
    const float* __restrict__ gWhb, const float* __restrict__ gbhb,
    const float* __restrict__ ghv,  const float* __restrict__ gscale,
    float* __restrict__ out)
{
    const int t = threadIdx.x;
    const int lane = t & 31;

    // Dynamic SMEM: second halves of W0 / W3 rows, thread-interleaved [8][128] (16 KB each)
    extern __shared__ __align__(16) unsigned char dynsmem[];
    ulonglong2* sw0 = reinterpret_cast<ulonglong2*>(dynsmem);            // [8][128]
    ulonglong2* sw3 = reinterpret_cast<ulonglong2*>(dynsmem) + 8 * 128;  // [8][128]

    __shared__ __align__(16) float sh[2][64];    // predicted mid-interval h (double buf)
    __shared__ __align__(16) float sz0[2][128];  // layer-0 out (double buf)
    __shared__ __align__(16) float sz1[2][128];
    __shared__ __align__(16) float sz2[2][128];
    __shared__ __align__(16) float swhb[64];
    __shared__ float sdt[200];

    float* out_state = out;          // (201, 5)
    float* out_h     = out + 201*5;  // (201, 64)

    // ---- weight registers: FULL W1/W2 row (64 ull) + first half of W0/W3 (16 ull) ----
    ull wreg[64];
    ull waux[16];          // W0[t][0:32] (group A) or W3half[0:32] (group B)
    float rb_main = 0.f;   // b1[t] or b2[u]
    float rb_aux  = 0.f;   // b0[t] (group A) or b3[u>>1] (group B leader)
    if (t < 128) {
        const float4* p1 = reinterpret_cast<const float4*>(gW1 + t * 128);
        #pragma unroll
        for (int j = 0; j < 32; j++) {
            float4 v = p1[j];
            wreg[2*j]   = pack2(v.x, v.y);
            wreg[2*j+1] = pack2(v.z, v.w);
        }
        rb_main = gb1[t];
        rb_aux  = gb0[t];
        const float4* p0 = reinterpret_cast<const float4*>(gW0 + t * 64);
        #pragma unroll
        for (int j = 0; j < 8; j++) {              // first 32 floats -> regs
            float4 v = p0[j];
            waux[2*j]   = pack2(v.x, v.y);
            waux[2*j+1] = pack2(v.z, v.w);
        }
        #pragma unroll
        for (int j = 0; j < 8; j++) {              // last 32 floats -> SMEM
            float4 v = p0[8 + j];
            ulonglong2 u2; u2.x = pack2(v.x, v.y); u2.y = pack2(v.z, v.w);
            sw0[j * 128 + t] = u2;
        }
    } else if (t < 256) {
        const int u = t - 128;
        const float4* p2 = reinterpret_cast<const float4*>(gW2 + u * 128);
        #pragma unroll
        for (int j = 0; j < 32; j++) {
            float4 v = p2[j];
            wreg[2*j]   = pack2(v.x, v.y);
            wreg[2*j+1] = pack2(v.z, v.w);
        }
        rb_main = gb2[u];
        rb_aux  = gb3[u >> 1];
        const float4* p3 = reinterpret_cast<const float4*>(gW3 + (u >> 1) * 128 + (u & 1) * 64);
        #pragma unroll
        for (int j = 0; j < 8; j++) {              // first 32 floats -> regs
            float4 v = p3[j];
            waux[2*j]   = pack2(v.x, v.y);
            waux[2*j+1] = pack2(v.z, v.w);
        }
        #pragma unroll
        for (int j = 0; j < 8; j++) {              // last 32 floats -> SMEM
            float4 v = p3[8 + j];
            ulonglong2 u2; u2.x = pack2(v.x, v.y); u2.y = pack2(v.z, v.w);
            sw3[j * 128 + u] = u2;
        }
    } else {
        for (int i = t - 256; i < 64; i += 32) swhb[i] = gWhb[i];
    }
    const float scl = gscale[0];
    const float bhb = gbhb[0];

    // ---- zero activation buffers, init h / state / dt / save 0 ----
    for (int i = t; i < 128; i += 288) {
        sz0[0][i] = 0.f; sz0[1][i] = 0.f;
        sz1[0][i] = 0.f; sz1[1][i] = 0.f;
        sz2[0][i] = 0.f; sz2[1][i] = 0.f;
    }
    float hreg = 0.0f;   // owned by group-B even threads: h[(t-128)>>1]
    if (t >= 128 && t < 256 && !(t & 1)) {
        int r = (t - 128) >> 1;
        hreg = ghv[r];
        sh[0][r] = hreg; sh[1][r] = hreg;
        out_h[r] = hreg;                  // save index 0, hidden part
    }
    float S = 0.f, E = 0.f, I = 0.f, A = 0.f, R = 0.f;
    float bs_prev = 0.f;
    if (t == 256) {
        S = y0[0]; E = y0[1]; I = y0[2]; A = y0[3]; R = y0[4];
        out_state[0] = S; out_state[1] = E; out_state[2] = I;
        out_state[3] = A; out_state[4] = R;
    }
    #pragma unroll 1
    for (int i = t; i < 200; i += 288) sdt[i] = ts[i + 1] - ts[i];
    __syncthreads();

    // ---- pipelined main loop: ONE phase per interval (+3 warmup fills) ----
    #pragma unroll 1
    for (int k = 0; k < 203; k++) {
        const int iv = k - 3;
        const int q  = k & 1;        // write buffer
        const int p  = q ^ 1;        // read buffer
        const float dtb = sdt[iv < 0 ? 0 : iv];

        if (t < 128) {
            // ----- W1 row t (FULL 128): z1[q][t] = softplus(W1[t,:] @ z0[p] + b1) -----
            {
                ull a0 = 0, a1 = 0, a2 = 0, a3 = 0;
                const ulonglong2* zin = reinterpret_cast<const ulonglong2*>(sz0[p]);
                #pragma unroll
                for (int j = 0; j < 32; j += 2) {
                    ulonglong2 z0v = zin[j], z1v = zin[j + 1];
                    FMA2(a0, wreg[2*j+0], z0v.x); FMA2(a1, wreg[2*j+1], z0v.y);
                    FMA2(a2, wreg[2*j+2], z1v.x); FMA2(a3, wreg[2*j+3], z1v.y);
                }
                ull s01, s23, stot;
                ADD2(s01, a0, a1); ADD2(s23, a2, a3); ADD2(stot, s01, s23);
                float lo, hi; unpack2(stot, lo, hi);
                sz1[q][t] = softplus_f(lo + hi + rb_main);
            }
            // ----- W0 row t: z0[q][t] = softplus(W0[t,:] @ h_pred[p] + b0) -----
            {
                // issue SMEM weight loads first so latency hides under reg FMAs
                ulonglong2 wv0 = sw0[0*128 + t], wv1 = sw0[1*128 + t];
                ulonglong2 wv2 = sw0[2*128 + t], wv3 = sw0[3*128 + t];
                ulonglong2 wv4 = sw0[4*128 + t], wv5 = sw0[5*128 + t];
                ulonglong2 wv6 = sw0[6*128 + t], wv7 = sw0[7*128 + t];
                const ulonglong2* hin = reinterpret_cast<const ulonglong2*>(sh[p]);
                ull a0 = 0, a1 = 0, a2 = 0, a3 = 0;
                #pragma unroll
                for (int j = 0; j < 8; j += 2) {       // reg half: h[0:32]
                    ulonglong2 h0 = hin[j], h1 = hin[j + 1];
                    FMA2(a0, waux[2*j+0], h0.x); FMA2(a1, waux[2*j+1], h0.y);
                    FMA2(a2, waux[2*j+2], h1.x); FMA2(a3, waux[2*j+3], h1.y);
                }
                {                                       // smem half: h[32:64]
                    ulonglong2 h0 = hin[8],  h1 = hin[9],  h2 = hin[10], h3 = hin[11];
                    ulonglong2 h4 = hin[12], h5 = hin[13], h6 = hin[14], h7 = hin[15];
                    FMA2(a0, wv0.x, h0.x); FMA2(a1, wv0.y, h0.y);
                    FMA2(a2, wv1.x, h1.x); FMA2(a3, wv1.y, h1.y);
                    FMA2(a0, wv2.x, h2.x); FMA2(a1, wv2.y, h2.y);
                    FMA2(a2, wv3.x, h3.x); FMA2(a3, wv3.y, h3.y);
                    FMA2(a0, wv4.x, h4.x); FMA2(a1, wv4.y, h4.y);
                    FMA2(a2, wv5.x, h5.x); FMA2(a3, wv5.y, h5.y);
                    FMA2(a0, wv6.x, h6.x); FMA2(a1, wv6.y, h6.y);
                    FMA2(a2, wv7.x, h7.x); FMA2(a3, wv7.y, h7.y);
                }
                ull s01, s23, stot;
                ADD2(s01, a0, a1); ADD2(s23, a2, a3); ADD2(stot, s01, s23);
                float lo, hi; unpack2(stot, lo, hi);
                sz0[q][t] = softplus_f(lo + hi + rb_aux);
            }
        } else if (t < 256) {
            const int u = t - 128;
            // ----- W2 row u (FULL 128): z2[q][u] = softplus(W2[u,:] @ z1[p] + b2) -----
            {
                ull a0 = 0, a1 = 0, a2 = 0, a3 = 0;
                const ulonglong2* zin = reinterpret_cast<const ulonglong2*>(sz1[p]);
                #pragma unroll
                for (int j = 0; j < 32; j += 2) {
                    ulonglong2 z0v = zin[j], z1v = zin[j + 1];
                    FMA2(a0, wreg[2*j+0], z0v.x); FMA2(a1, wreg[2*j+1], z0v.y);
                    FMA2(a2, wreg[2*j+2], z1v.x); FMA2(a3, wreg[2*j+3], z1v.y);
                }
                ull s01, s23, stot;
                ADD2(s01, a0, a1); ADD2(s23, a2, a3); ADD2(stot, s01, s23);
                float lo, hi; unpack2(stot, lo, hi);
                sz2[q][u] = softplus_f(lo + hi + rb_main);
            }
            // ----- W3 half-row: o[u>>1] partial over z2[p][ (u&1)*64 .. +63 ] -----
            {
                ulonglong2 wv0 = sw3[0*128 + u], wv1 = sw3[1*128 + u];
                ulonglong2 wv2 = sw3[2*128 + u], wv3 = sw3[3*128 + u];
                ulonglong2 wv4 = sw3[4*128 + u], wv5 = sw3[5*128 + u];
                ulonglong2 wv6 = sw3[6*128 + u], wv7 = sw3[7*128 + u];
                const ulonglong2* zin =
                    reinterpret_cast<const ulonglong2*>(sz2[p] + (u & 1) * 64);
                ull a0 = 0, a1 = 0, a2 = 0, a3 = 0;
                #pragma unroll
                for (int j = 0; j < 8; j += 2) {       // reg half
                    ulonglong2 z0v = zin[j], z1v = zin[j + 1];
                    FMA2(a0, waux[2*j+0], z0v.x); FMA2(a1, waux[2*j+1], z0v.y);
                    FMA2(a2, waux[2*j+2], z1v.x); FMA2(a3, waux[2*j+3], z1v.y);
                }
                {                                       // smem half
                    ulonglong2 z0v = zin[8],  z1v = zin[9],  z2v = zin[10], z3v = zin[11];
                    ulonglong2 z4v = zin[12], z5v = zin[13], z6v = zin[14], z7v = zin[15];
                    FMA2(a0, wv0.x, z0v.x); FMA2(a1, wv0.y, z0v.y);
                    FMA2(a2, wv1.x, z1v.x); FMA2(a3, wv1.y, z1v.y);
                    FMA2(a0, wv2.x, z2v.x); FMA2(a1, wv2.y, z2v.y);
                    FMA2(a2, wv3.x, z3v.x); FMA2(a3, wv3.y, z3v.y);
                    FMA2(a0, wv4.x, z4v.x); FMA2(a1, wv4.y, z4v.y);
                    FMA2(a2, wv5.x, z5v.x); FMA2(a3, wv5.y, z5v.y);
                    FMA2(a0, wv6.x, z6v.x); FMA2(a1, wv6.y, z6v.y);
                    FMA2(a2, wv7.x, z7v.x); FMA2(a3, wv7.y, z7v.y);
                }
                ull s01, s23, stot;
                ADD2(s01, a0, a1); ADD2(s23, a2, a3); ADD2(stot, s01, s23);
                float lo, hi; unpack2(stot, lo, hi);
                float half = lo + hi;
                half += __shfl_xor_sync(FULLMASK, half, 1);
                if (!(u & 1)) {
                    const int r = u >> 1;
                    float o  = half + rb_aux;
                    float kH = scl * tanhf(1e-4f * o);
                    if (iv >= 0) {
                        hreg = fmaf(dtb, kH, hreg);            // midpoint update of true h
                        sh[q][r] = fmaf(0.5f * dtb, kH, hreg); // next interval's h_mid
                        out_h[(iv + 1) * 64 + r] = hreg;
                    } else {
                        sh[q][r] = hreg;                       // warmup: keep h0
                    }
                }
            }
        } else {
            // ----- warp 8: bs reduce (16 lanes); lanes 0-2: betas in parallel;
            //       lane 0: 3 SEIR substeps + save -----
            if (iv >= 0) {
                float bs = 0.f;
                if (lane < 16) {
                    const ulonglong2 h2 = *reinterpret_cast<const ulonglong2*>(sh[p] + lane * 4);
                    const ulonglong2 ww = *reinterpret_cast<const ulonglong2*>(swhb + lane * 4);
                    ull c0 = 0, c1 = 0;
                    FMA2(c0, ww.x, h2.x); FMA2(c1, ww.y, h2.y);
                    ull cs; ADD2(cs, c0, c1);
                    float cl, ch; unpack2(cs, cl, ch);
                    bs = cl + ch;
                    bs += __shfl_xor_sync(0x0000FFFFu, bs, 1);
                    bs += __shfl_xor_sync(0x0000FFFFu, bs, 2);
                    bs += __shfl_xor_sync(0x0000FFFFu, bs, 4);
                    bs += __shfl_xor_sync(0x0000FFFFu, bs, 8);
                    // lanes 0-2 compute their beta in parallel (all lanes have same bs)
                    float dbs = (iv > 0) ? (bs - bs_prev) : 0.0f;
                    bs_prev = bs;
                    float fr = (lane == 0) ? -0.33333334f
                             : ((lane == 1) ? 0.0f : 0.33333334f);
                    float beta_l = sigmoid_f(fmaf(fr, dbs, bs) + bhb);
                    float b1v = __shfl_sync(0x0000FFFFu, beta_l, 1);
                    float b2v = __shfl_sync(0x0000FFFFu, beta_l, 2);
                    if (lane == 0) {
                        const float hsub = dtb * (1.0f / 3.0f);
                        seir_step(hsub, beta_l, S, E, I, A, R);
                        seir_step(hsub, b1v,    S, E, I, A, R);
                        seir_step(hsub, b2v,    S, E, I, A, R);
                        float* os = out_state + (iv + 1) * 5;
                        os[0] = S; os[1] = E; os[2] = I; os[3] = A; os[4] = R;
                    }
                }
            }
        }
        __syncthreads();
    } // pipeline loop
}

extern "C" void kernel_launch(void* const* d_in, const int* in_sizes, int n_in,
                              void* d_out, int out_size) {
    (void)in_sizes; (void)n_in; (void)out_size;
    const float* y0   = (const float*)d_in[0];
    const float* ts   = (const float*)d_in[1];
    const float* W0   = (const float*)d_in[2];
    const float* b0   = (const float*)d_in[3];
    const float* W1   = (const float*)d_in[4];
    const float* b1   = (const float*)d_in[5];
    const float* W2   = (const float*)d_in[6];
    const float* b2   = (const float*)d_in[7];
    const float* W3   = (const float*)d_in[8];
    const float* b3   = (const float*)d_in[9];
    const float* Whb  = (const float*)d_in[10];
    const float* bhb  = (const float*)d_in[11];
    const float* hv   = (const float*)d_in[12];
    const float* scal = (const float*)d_in[13];
    float* out = (float*)d_out;

    const int dyn_smem = 2 * 8 * 128 * 16;  // sw0 + sw3 = 32 KB
    cudaFuncSetAttribute(ode_persistent_kernel,
                         cudaFuncAttributeMaxDynamicSharedMemorySize, dyn_smem);
    ode_persistent_kernel<<<1, 288, dyn_smem>>>(y0, ts, W0, b0, W1, b1, W2, b2, W3, b3,
                                                Whb, bhb, hv, scal, out);
}